// round 15
// baseline (speedup 1.0000x reference)
#include <cuda_runtime.h>
#include <cuda_fp16.h>
#include <stdint.h>

// ---------------- scratch (__device__ globals; no allocations anywhere) ----
__device__ __half g_xh [4096u * 2048u];   // x transposed: row (b,p), K=2048 contiguous, fp16
__device__ __half g_w1t[512u  * 2048u];   // Wg1 as [n][k] fp16
__device__ __half g_w2t[256 * 256];       // Wg2^T fp16 [n][k]
__device__ __half g_w3t[256 * 256];
__device__ __half g_w4t[256 * 256];
__device__ __half g_AB [4096u * 512u];    // GEMM1 out: [(b,p)][512] (A | B)
__device__ float  g_part[1024 * 256];     // per-CTA partial column sums

__device__ __forceinline__ uint32_t cvta_s(const void* p) {
    return (uint32_t)__cvta_generic_to_shared(p);
}
__device__ __forceinline__ void ldsm_x4(uint32_t& r0, uint32_t& r1, uint32_t& r2, uint32_t& r3,
                                        uint32_t addr) {
    asm volatile("ldmatrix.sync.aligned.m8n8.x4.shared.b16 {%0,%1,%2,%3}, [%4];\n"
                 : "=r"(r0), "=r"(r1), "=r"(r2), "=r"(r3) : "r"(addr));
}
#define MMA16816(acc, af, b0, b1)                                              \
    asm volatile(                                                              \
        "mma.sync.aligned.m16n8k16.row.col.f32.f16.f16.f32 "                   \
        "{%0,%1,%2,%3}, {%4,%5,%6,%7}, {%8,%9}, {%0,%1,%2,%3};\n"              \
        : "+f"(acc[0]), "+f"(acc[1]), "+f"(acc[2]), "+f"(acc[3])               \
        : "r"(af[0]), "r"(af[1]), "r"(af[2]), "r"(af[3]), "r"(b0), "r"(b1))

// ---------------- k_pre: ALL weight/input transposes in one launch ----------
__global__ void k_pre(const float* __restrict__ x, const float* __restrict__ Wg1,
                      const float* __restrict__ W2, const float* __restrict__ W3,
                      const float* __restrict__ W4)
{
    __shared__ float t[32][33];
    const int id = blockIdx.x;
    const float* inb; __half* outb; int R, C, r0, c0;
    if (id < 8192) {
        int z = id >> 6, yb = id & 63;
        inb = x + (size_t)z * 2048 * 32;
        outb = g_xh + (size_t)z * 2048 * 32;
        R = 2048; C = 32; r0 = yb * 32; c0 = 0;
    } else if (id < 9216) {
        int w = id - 8192;
        int half = w >> 9, rem = w & 511;
        int xb = rem & 7, yb = rem >> 3;
        inb = Wg1 + (size_t)half * 2048 * 256;
        outb = g_w1t + (size_t)half * 256 * 2048;
        R = 2048; C = 256; r0 = yb * 32; c0 = xb * 32;
    } else {
        int w = id - 9216;
        int which = w >> 6, rem = w & 63;
        int xb = rem & 7, yb = rem >> 3;
        const float* src[3] = {W2, W3, W4};
        __half* dst[3] = {g_w2t, g_w3t, g_w4t};
        inb = src[which]; outb = dst[which];
        R = 256; C = 256; r0 = yb * 32; c0 = xb * 32;
    }
    for (int i = threadIdx.y; i < 32; i += 8)
        t[i][threadIdx.x] = inb[(size_t)(r0 + i) * C + c0 + threadIdx.x];
    __syncthreads();
    for (int i = threadIdx.y; i < 32; i += 8)
        outb[(size_t)(c0 + i) * R + r0 + threadIdx.x] = __float2half(t[threadIdx.x][i]);
}

// ---------------- GEMM1: pipelined fp16 HMMA, BM=128 BN=128 BK=64 ----------
static const int G1_SMEM = 2 * (128 * 72 * 2) * 2;   // 73728 B

__device__ __forceinline__ void g1_issue(const __half* __restrict__ Ag,
                                         const __half* __restrict__ Bg,
                                         __half (*sA)[72], __half (*sB)[72],
                                         int K, int k0, int tid)
{
    #pragma unroll
    for (int it = 0; it < 4; it++) {
        int idx = it * 256 + tid;
        int row = idx >> 3, c8 = (idx & 7) * 8;
        asm volatile("cp.async.cg.shared.global [%0], [%1], 16;\n"
                     :: "r"(cvta_s(&sA[row][c8])), "l"(Ag + (size_t)row * K + k0 + c8));
        asm volatile("cp.async.cg.shared.global [%0], [%1], 16;\n"
                     :: "r"(cvta_s(&sB[row][c8])), "l"(Bg + (size_t)row * K + k0 + c8));
    }
    asm volatile("cp.async.commit_group;\n");
}

__global__ __launch_bounds__(256) void k_gemm1(const __half* __restrict__ A,
                                               const __half* __restrict__ Bt,
                                               __half* __restrict__ C,
                                               int M, int N, int K)
{
    extern __shared__ char dyn[];
    __half (*sA)[128][72] = (__half(*)[128][72])dyn;
    __half (*sB)[128][72] = (__half(*)[128][72])(dyn + 2 * 128 * 72 * 2);

    const int m0 = blockIdx.y * 128, n0 = blockIdx.x * 128;
    const int tid = threadIdx.x, warp = tid >> 5, lane = tid & 31;
    const int wm0 = (warp & 3) * 32;
    const int wn0 = (warp >> 2) * 64;
    const int g = lane >> 2, c2 = (lane & 3) * 2;

    const __half* Ag = A  + (size_t)m0 * K;
    const __half* Bg = Bt + (size_t)n0 * K;

    float acc[2][8][4];
    #pragma unroll
    for (int mt = 0; mt < 2; mt++)
        #pragma unroll
        for (int nt = 0; nt < 8; nt++)
            #pragma unroll
            for (int q = 0; q < 4; q++) acc[mt][nt][q] = 0.f;

    uint32_t aOff[2], bOff[4];
    #pragma unroll
    for (int mt = 0; mt < 2; mt++)
        aOff[mt] = ((wm0 + mt * 16 + (lane & 15)) * 72 + (lane >> 4) * 8) * 2;
    #pragma unroll
    for (int p = 0; p < 4; p++)
        bOff[p] = ((wn0 + p * 16 + ((lane >> 4) & 1) * 8 + (lane & 7)) * 72
                   + ((lane >> 3) & 1) * 8) * 2;
    const uint32_t sAb = cvta_s(sA), sBb = cvta_s(sB);
    const uint32_t stgA = 128 * 72 * 2;

    const int NC = K / 64;
    g1_issue(Ag, Bg, sA[0], sB[0], K, 0, tid);

    for (int kc = 0; kc < NC; kc++) {
        if (kc + 1 < NC) {
            g1_issue(Ag, Bg, sA[(kc + 1) & 1], sB[(kc + 1) & 1], K, (kc + 1) * 64, tid);
            asm volatile("cp.async.wait_group 1;\n" ::: "memory");
        } else {
            asm volatile("cp.async.wait_group 0;\n" ::: "memory");
        }
        __syncthreads();
        const uint32_t abase = sAb + (kc & 1) * stgA;
        const uint32_t bbase = sBb + (kc & 1) * stgA;
        #pragma unroll
        for (int kk = 0; kk < 64; kk += 16) {
            uint32_t af[2][4], bf[8][2];
            #pragma unroll
            for (int mt = 0; mt < 2; mt++)
                ldsm_x4(af[mt][0], af[mt][1], af[mt][2], af[mt][3],
                        abase + aOff[mt] + kk * 2);
            #pragma unroll
            for (int p = 0; p < 4; p++)
                ldsm_x4(bf[2*p][0], bf[2*p][1], bf[2*p+1][0], bf[2*p+1][1],
                        bbase + bOff[p] + kk * 2);
            #pragma unroll
            for (int mt = 0; mt < 2; mt++)
                #pragma unroll
                for (int nt = 0; nt < 8; nt++)
                    MMA16816(acc[mt][nt], af[mt], bf[nt][0], bf[nt][1]);
        }
        __syncthreads();
    }

    #pragma unroll
    for (int mt = 0; mt < 2; mt++) {
        int row = m0 + wm0 + mt * 16 + g;
        #pragma unroll
        for (int nt = 0; nt < 8; nt++) {
            int col = n0 + wn0 + nt * 8 + c2;
            *(__half2*)&C[(size_t)row       * N + col] = __floats2half2_rn(acc[mt][nt][0], acc[mt][nt][1]);
            *(__half2*)&C[(size_t)(row + 8) * N + col] = __floats2half2_rn(acc[mt][nt][2], acc[mt][nt][3]);
        }
    }
}

// ---------------- fused pairwise stage --------------------------------------
// EXACT 309.2us-winner config: 256 thr, 8 warps, warp tile 64x64,
// weight chunk 32 (8 per layer), smem 110KB.
static const int SMEM_FUSED = 128*264*2 + 2*256*40*2 + 2*256*4;

__device__ __forceinline__ void prefetch_w(const __half* __restrict__ Wt, int kc,
                                           __half (*sWbuf)[40], int tid)
{
    #pragma unroll
    for (int it = 0; it < 4; it++) {
        int idx = it * 256 + tid;
        int n = idx >> 2, c4 = idx & 3;
        asm volatile("cp.async.cg.shared.global [%0], [%1], 16;\n"
                     :: "r"(cvta_s(&sWbuf[n][c4 * 8])), "l"(Wt + n * 256 + kc * 32 + c4 * 8));
    }
    asm volatile("cp.async.commit_group;\n");
}

__global__ __launch_bounds__(256, 1) void k_fused(const float* __restrict__ bg1,
                                                  const float* __restrict__ bg2,
                                                  const float* __restrict__ bg3,
                                                  const float* __restrict__ bg4)
{
    extern __shared__ char smem[];
    __half (*sAct)[264]   = (__half(*)[264])smem;
    __half (*sW)[256][40] = (__half(*)[256][40])(smem + 128*264*2);
    float*  sCol          = (float*)(smem + 128*264*2 + 2*256*40*2);

    const int tid  = threadIdx.x;
    const int warp = tid >> 5, lane = tid & 31;
    const int g    = lane >> 2, c2 = (lane & 3) * 2;
    const int wm0  = (warp & 1) * 64;
    const int wn0  = (warp >> 1) * 64;
    const int ct   = blockIdx.x;
    const int b    = ct >> 3;
    const int i0   = (ct & 7) * 4;

    const __half* wts[3]    = {g_w2t, g_w3t, g_w4t};
    const float*  biases[3] = {bg2, bg3, bg4};

    prefetch_w(wts[0], 0, sW[0], tid);

    // ---- build: act[m][d] = relu(A[b,j,d] + B[b,i,d] + bg1[d]) ----
    {
        int m = tid >> 1, half = tid & 1;
        int i = i0 + (m >> 5), j = m & 31;
        const __half2* Ar = (const __half2*)g_AB + (size_t)(b * 32 + j) * 256 + half * 64;
        const __half2* Br = (const __half2*)g_AB + (size_t)(b * 32 + i) * 256 + 128 + half * 64;
        const float2*  bb = (const float2*)bg1 + half * 64;
        __half2* dst = (__half2*)&sAct[m][half * 128];
        #pragma unroll 8
        for (int cc = 0; cc < 64; cc++) {
            float2 a = __half22float2(Ar[cc]);
            float2 e = __half22float2(Br[cc]);
            float2 bi = bb[cc];
            dst[cc] = __floats2half2_rn(fmaxf(a.x + e.x + bi.x, 0.f),
                                        fmaxf(a.y + e.y + bi.y, 0.f));
        }
    }

    uint32_t aAddr[4], bOff[4];
    #pragma unroll
    for (int mt = 0; mt < 4; mt++)
        aAddr[mt] = cvta_s(&sAct[wm0 + mt * 16 + (lane & 15)][(lane >> 4) * 8]);
    #pragma unroll
    for (int p = 0; p < 4; p++)
        bOff[p] = ((wn0 + p * 16 + ((lane >> 4) & 1) * 8 + (lane & 7)) * 40
                   + ((lane >> 3) & 1) * 8) * 2;
    const uint32_t sWb = cvta_s(sW);
    const uint32_t wBufSz = 256 * 40 * 2;

    for (int L = 0; L < 3; L++) {
        const __half* Wt  = wts[L];
        const float* bias = biases[L];

        float acc[4][8][4];
        #pragma unroll
        for (int mt = 0; mt < 4; mt++)
            #pragma unroll
            for (int nt = 0; nt < 8; nt++)
                #pragma unroll
                for (int q = 0; q < 4; q++) acc[mt][nt][q] = 0.f;

        for (int kc = 0; kc < 8; kc++) {
            asm volatile("cp.async.wait_group 0;\n" ::: "memory");
            __syncthreads();
            if (kc < 7)     prefetch_w(Wt,       kc + 1, sW[(kc + 1) & 1], tid);
            else if (L < 2) prefetch_w(wts[L+1], 0,      sW[0],            tid);
            const uint32_t bbase = sWb + (kc & 1) * wBufSz;

            #pragma unroll
            for (int kk = 0; kk < 32; kk += 16) {
                const int kbase = kc * 32 + kk;
                uint32_t af[4][4], bf[8][2];
                #pragma unroll
                for (int mt = 0; mt < 4; mt++)
                    ldsm_x4(af[mt][0], af[mt][1], af[mt][2], af[mt][3],
                            aAddr[mt] + kbase * 2);
                #pragma unroll
                for (int p = 0; p < 4; p++)
                    ldsm_x4(bf[2*p][0], bf[2*p][1], bf[2*p+1][0], bf[2*p+1][1],
                            bbase + bOff[p] + kk * 2);
                #pragma unroll
                for (int mt = 0; mt < 4; mt++)
                    #pragma unroll
                    for (int nt = 0; nt < 8; nt++)
                        MMA16816(acc[mt][nt], af[mt], bf[nt][0], bf[nt][1]);
            }
        }
        __syncthreads();   // all warps done reading sAct for this layer

        if (L < 2) {
            #pragma unroll
            for (int mt = 0; mt < 4; mt++) {
                int row = wm0 + mt * 16 + g;
                #pragma unroll
                for (int nt = 0; nt < 8; nt++) {
                    int col = wn0 + nt * 8 + c2;
                    float b0 = bias[col], b1 = bias[col + 1];
                    *(__half2*)&sAct[row    ][col] =
                        __floats2half2_rn(fmaxf(acc[mt][nt][0] + b0, 0.f),
                                          fmaxf(acc[mt][nt][1] + b1, 0.f));
                    *(__half2*)&sAct[row + 8][col] =
                        __floats2half2_rn(fmaxf(acc[mt][nt][2] + b0, 0.f),
                                          fmaxf(acc[mt][nt][3] + b1, 0.f));
                }
            }
        } else {
            #pragma unroll
            for (int nt = 0; nt < 8; nt++) {
                int col = wn0 + nt * 8 + c2;
                float b0 = bias[col], b1 = bias[col + 1];
                float s0 = 0.f, s1 = 0.f;
                #pragma unroll
                for (int mt = 0; mt < 4; mt++) {
                    s0 += fmaxf(acc[mt][nt][0] + b0, 0.f) + fmaxf(acc[mt][nt][2] + b0, 0.f);
                    s1 += fmaxf(acc[mt][nt][1] + b1, 0.f) + fmaxf(acc[mt][nt][3] + b1, 0.f);
                }
                #pragma unroll
                for (int o = 4; o < 32; o <<= 1) {
                    s0 += __shfl_xor_sync(0xffffffffu, s0, o);
                    s1 += __shfl_xor_sync(0xffffffffu, s1, o);
                }
                if (lane < 4) {
                    sCol[(warp & 1) * 256 + wn0 + nt * 8 + lane * 2    ] = s0;
                    sCol[(warp & 1) * 256 + wn0 + nt * 8 + lane * 2 + 1] = s1;
                }
            }
            __syncthreads();
            g_part[(size_t)ct * 256 + tid] = sCol[tid] + sCol[256 + tid];
        }
    }
}

// ---------------- fused fp32 tail: part-sum -> 3 dense layers (per-row) -----
// 8-way k-unrolled independent accumulators: converts the 256-deep serial
// FMA+load chain into 8 parallel chains with batched (MLP=8) loads.
__global__ void k_tails(const float* __restrict__ Wf1,  const float* __restrict__ bf1,
                        const float* __restrict__ Wfc2, const float* __restrict__ bfc2,
                        const float* __restrict__ Wfc3, const float* __restrict__ bfc3,
                        float* __restrict__ out)
{
    __shared__ float s0[256], s1[256];
    int b = blockIdx.x, n = threadIdx.x;
    float a = 0.f;
    #pragma unroll
    for (int s = 0; s < 8; s++) a += g_part[(size_t)(b * 8 + s) * 256 + n];
    s0[n] = a;
    __syncthreads();

    // layer 1: s1 = relu(s0 @ Wf1 + bf1)
    {
        float p[8] = {0.f, 0.f, 0.f, 0.f, 0.f, 0.f, 0.f, 0.f};
        for (int k0 = 0; k0 < 256; k0 += 8) {
            #pragma unroll
            for (int u = 0; u < 8; u++)
                p[u] = fmaf(s0[k0 + u], Wf1[(size_t)(k0 + u) * 256 + n], p[u]);
        }
        float acc = bf1[n] + ((p[0] + p[1]) + (p[2] + p[3]))
                           + ((p[4] + p[5]) + (p[6] + p[7]));
        s1[n] = fmaxf(acc, 0.f);
    }
    __syncthreads();

    // layer 2: s0 = relu(s1 @ Wfc2 + bfc2)
    {
        float p[8] = {0.f, 0.f, 0.f, 0.f, 0.f, 0.f, 0.f, 0.f};
        for (int k0 = 0; k0 < 256; k0 += 8) {
            #pragma unroll
            for (int u = 0; u < 8; u++)
                p[u] = fmaf(s1[k0 + u], Wfc2[(size_t)(k0 + u) * 256 + n], p[u]);
        }
        float acc = bfc2[n] + ((p[0] + p[1]) + (p[2] + p[3]))
                            + ((p[4] + p[5]) + (p[6] + p[7]));
        s0[n] = fmaxf(acc, 0.f);
    }
    __syncthreads();

    // layer 3: out = s0 @ Wfc3 + bfc3  (128 cols; 2 threads per col over k-halves)
    {
        int col = n & 127, half = n >> 7;   // half: k in [half*128, half*128+128)
        float p[8] = {0.f, 0.f, 0.f, 0.f, 0.f, 0.f, 0.f, 0.f};
        int kb = half * 128;
        for (int k0 = 0; k0 < 128; k0 += 8) {
            #pragma unroll
            for (int u = 0; u < 8; u++)
                p[u] = fmaf(s0[kb + k0 + u], Wfc3[(size_t)(kb + k0 + u) * 128 + col], p[u]);
        }
        float part = ((p[0] + p[1]) + (p[2] + p[3])) + ((p[4] + p[5]) + (p[6] + p[7]));
        s1[n] = part;
        __syncthreads();
        if (half == 0)
            out[(size_t)b * 128 + col] = bfc3[col] + s1[col] + s1[col + 128];
    }
}

// ---------------- host ------------------------------------------------------
extern "C" void kernel_launch(void* const* d_in, const int* in_sizes, int n_in,
                              void* d_out, int out_size)
{
    const float* x    = (const float*)d_in[0];
    const float* Wg1  = (const float*)d_in[1];
    const float* bg1  = (const float*)d_in[2];
    const float* Wg2  = (const float*)d_in[3];
    const float* bg2  = (const float*)d_in[4];
    const float* Wg3  = (const float*)d_in[5];
    const float* bg3  = (const float*)d_in[6];
    const float* Wg4  = (const float*)d_in[7];
    const float* bg4  = (const float*)d_in[8];
    const float* Wf1  = (const float*)d_in[9];
    const float* bf1  = (const float*)d_in[10];
    const float* Wfc2 = (const float*)d_in[11];
    const float* bfc2 = (const float*)d_in[12];
    const float* Wfc3 = (const float*)d_in[13];
    const float* bfc3 = (const float*)d_in[14];
    float* out = (float*)d_out;

    __half *xh, *w1t, *AB;
    cudaGetSymbolAddress((void**)&xh,  g_xh);
    cudaGetSymbolAddress((void**)&w1t, g_w1t);
    cudaGetSymbolAddress((void**)&AB,  g_AB);

    cudaFuncSetAttribute(k_fused, cudaFuncAttributeMaxDynamicSharedMemorySize, SMEM_FUSED);
    cudaFuncSetAttribute(k_gemm1, cudaFuncAttributeMaxDynamicSharedMemorySize, G1_SMEM);

    dim3 tb(32, 8);
    k_pre<<<9408, tb>>>(x, Wg1, Wg2, Wg3, Wg4);                                 // 1
    k_gemm1<<<dim3(4, 32), 256, G1_SMEM>>>(xh, w1t, AB, 4096, 512, 2048);       // 2
    k_fused<<<1024, 256, SMEM_FUSED>>>(bg1, bg2, bg3, bg4);                     // 3
    k_tails<<<128, 256>>>(Wf1, bf1, Wfc2, bfc2, Wfc3, bfc3, out);               // 4
}

// round 16
// speedup vs baseline: 1.0517x; 1.0517x over previous
#include <cuda_runtime.h>
#include <cuda_fp16.h>
#include <stdint.h>

// ---------------- scratch (__device__ globals; no allocations anywhere) ----
__device__ __half g_xh [4096u * 2048u];   // x transposed: row (b,p), K=2048 contiguous, fp16
__device__ __half g_w1t[512u  * 2048u];   // Wg1 as [n][k] fp16
__device__ __half g_w2t[256 * 256];       // Wg2^T fp16 [n][k]
__device__ __half g_w3t[256 * 256];
__device__ __half g_w4t[256 * 256];
__device__ __half g_AB [4096u * 512u];    // GEMM1 out: [(b,p)][512] (A | B)
__device__ float  g_part[1024 * 256];     // per-CTA partial column sums
__device__ float  g_sink;                 // L2-warm discard target (never read)

__device__ __forceinline__ uint32_t cvta_s(const void* p) {
    return (uint32_t)__cvta_generic_to_shared(p);
}
__device__ __forceinline__ void ldsm_x4(uint32_t& r0, uint32_t& r1, uint32_t& r2, uint32_t& r3,
                                        uint32_t addr) {
    asm volatile("ldmatrix.sync.aligned.m8n8.x4.shared.b16 {%0,%1,%2,%3}, [%4];\n"
                 : "=r"(r0), "=r"(r1), "=r"(r2), "=r"(r3) : "r"(addr));
}
#define MMA16816(acc, af, b0, b1)                                              \
    asm volatile(                                                              \
        "mma.sync.aligned.m16n8k16.row.col.f32.f16.f16.f32 "                   \
        "{%0,%1,%2,%3}, {%4,%5,%6,%7}, {%8,%9}, {%0,%1,%2,%3};\n"              \
        : "+f"(acc[0]), "+f"(acc[1]), "+f"(acc[2]), "+f"(acc[3])               \
        : "r"(af[0]), "r"(af[1]), "r"(af[2]), "r"(af[3]), "r"(b0), "r"(b1))

// ---------------- k_pre: all transposes + tail-weight L2 warm (one launch) --
// id < 8192          : x batch z=id>>6, row-block id&63  (2048x32 per batch)
// 8192 <= id < 9216  : Wg1 half (id-8192)>>9, 8x64 blocks of 2048x256
// 9216 <= id < 9408  : W2/3/4 (id-9216)>>6, 8x8 blocks of 256x256
// 9408 <= id < 9488  : L2 warm of Wf1|Wfc2|Wfc3 (163840 floats, 2048/block)
__global__ void k_pre(const float* __restrict__ x, const float* __restrict__ Wg1,
                      const float* __restrict__ W2, const float* __restrict__ W3,
                      const float* __restrict__ W4,
                      const float* __restrict__ Wf1, const float* __restrict__ Wfc2,
                      const float* __restrict__ Wfc3)
{
    __shared__ float t[32][33];
    const int id = blockIdx.x;
    if (id >= 9408) {
        // L2 warm: stream tail weights; NaN-guard keeps loads alive (never true).
        int w = id - 9408;
        int tt = threadIdx.y * 32 + threadIdx.x;
        size_t g0 = (size_t)w * 2048 + (size_t)tt * 8;
        float s = 0.f;
        #pragma unroll
        for (int j = 0; j < 8; j++) {
            size_t g = g0 + j;
            float v;
            if (g < 65536)       v = Wf1 [g];
            else if (g < 131072) v = Wfc2[g - 65536];
            else                 v = Wfc3[g - 131072];
            s += v;
        }
        if (s != s) g_sink = s;
        return;
    }
    const float* inb; __half* outb; int R, C, r0, c0;
    if (id < 8192) {
        int z = id >> 6, yb = id & 63;
        inb = x + (size_t)z * 2048 * 32;
        outb = g_xh + (size_t)z * 2048 * 32;
        R = 2048; C = 32; r0 = yb * 32; c0 = 0;
    } else if (id < 9216) {
        int w = id - 8192;
        int half = w >> 9, rem = w & 511;
        int xb = rem & 7, yb = rem >> 3;
        inb = Wg1 + (size_t)half * 2048 * 256;
        outb = g_w1t + (size_t)half * 256 * 2048;
        R = 2048; C = 256; r0 = yb * 32; c0 = xb * 32;
    } else {
        int w = id - 9216;
        int which = w >> 6, rem = w & 63;
        int xb = rem & 7, yb = rem >> 3;
        const float* src[3] = {W2, W3, W4};
        __half* dst[3] = {g_w2t, g_w3t, g_w4t};
        inb = src[which]; outb = dst[which];
        R = 256; C = 256; r0 = yb * 32; c0 = xb * 32;
    }
    for (int i = threadIdx.y; i < 32; i += 8)
        t[i][threadIdx.x] = inb[(size_t)(r0 + i) * C + c0 + threadIdx.x];
    __syncthreads();
    for (int i = threadIdx.y; i < 32; i += 8)
        outb[(size_t)(c0 + i) * R + r0 + threadIdx.x] = __float2half(t[threadIdx.x][i]);
}

// ---------------- GEMM1: pipelined fp16 HMMA, BM=128 BN=128 BK=64 ----------
static const int G1_SMEM = 2 * (128 * 72 * 2) * 2;   // 73728 B

__device__ __forceinline__ void g1_issue(const __half* __restrict__ Ag,
                                         const __half* __restrict__ Bg,
                                         __half (*sA)[72], __half (*sB)[72],
                                         int K, int k0, int tid)
{
    #pragma unroll
    for (int it = 0; it < 4; it++) {
        int idx = it * 256 + tid;
        int row = idx >> 3, c8 = (idx & 7) * 8;
        asm volatile("cp.async.cg.shared.global [%0], [%1], 16;\n"
                     :: "r"(cvta_s(&sA[row][c8])), "l"(Ag + (size_t)row * K + k0 + c8));
        asm volatile("cp.async.cg.shared.global [%0], [%1], 16;\n"
                     :: "r"(cvta_s(&sB[row][c8])), "l"(Bg + (size_t)row * K + k0 + c8));
    }
    asm volatile("cp.async.commit_group;\n");
}

__global__ __launch_bounds__(256) void k_gemm1(const __half* __restrict__ A,
                                               const __half* __restrict__ Bt,
                                               __half* __restrict__ C,
                                               int M, int N, int K)
{
    extern __shared__ char dyn[];
    __half (*sA)[128][72] = (__half(*)[128][72])dyn;
    __half (*sB)[128][72] = (__half(*)[128][72])(dyn + 2 * 128 * 72 * 2);

    const int m0 = blockIdx.y * 128, n0 = blockIdx.x * 128;
    const int tid = threadIdx.x, warp = tid >> 5, lane = tid & 31;
    const int wm0 = (warp & 3) * 32;
    const int wn0 = (warp >> 2) * 64;
    const int g = lane >> 2, c2 = (lane & 3) * 2;

    const __half* Ag = A  + (size_t)m0 * K;
    const __half* Bg = Bt + (size_t)n0 * K;

    float acc[2][8][4];
    #pragma unroll
    for (int mt = 0; mt < 2; mt++)
        #pragma unroll
        for (int nt = 0; nt < 8; nt++)
            #pragma unroll
            for (int q = 0; q < 4; q++) acc[mt][nt][q] = 0.f;

    uint32_t aOff[2], bOff[4];
    #pragma unroll
    for (int mt = 0; mt < 2; mt++)
        aOff[mt] = ((wm0 + mt * 16 + (lane & 15)) * 72 + (lane >> 4) * 8) * 2;
    #pragma unroll
    for (int p = 0; p < 4; p++)
        bOff[p] = ((wn0 + p * 16 + ((lane >> 4) & 1) * 8 + (lane & 7)) * 72
                   + ((lane >> 3) & 1) * 8) * 2;
    const uint32_t sAb = cvta_s(sA), sBb = cvta_s(sB);
    const uint32_t stgA = 128 * 72 * 2;

    const int NC = K / 64;
    g1_issue(Ag, Bg, sA[0], sB[0], K, 0, tid);

    for (int kc = 0; kc < NC; kc++) {
        if (kc + 1 < NC) {
            g1_issue(Ag, Bg, sA[(kc + 1) & 1], sB[(kc + 1) & 1], K, (kc + 1) * 64, tid);
            asm volatile("cp.async.wait_group 1;\n" ::: "memory");
        } else {
            asm volatile("cp.async.wait_group 0;\n" ::: "memory");
        }
        __syncthreads();
        const uint32_t abase = sAb + (kc & 1) * stgA;
        const uint32_t bbase = sBb + (kc & 1) * stgA;
        #pragma unroll
        for (int kk = 0; kk < 64; kk += 16) {
            uint32_t af[2][4], bf[8][2];
            #pragma unroll
            for (int mt = 0; mt < 2; mt++)
                ldsm_x4(af[mt][0], af[mt][1], af[mt][2], af[mt][3],
                        abase + aOff[mt] + kk * 2);
            #pragma unroll
            for (int p = 0; p < 4; p++)
                ldsm_x4(bf[2*p][0], bf[2*p][1], bf[2*p+1][0], bf[2*p+1][1],
                        bbase + bOff[p] + kk * 2);
            #pragma unroll
            for (int mt = 0; mt < 2; mt++)
                #pragma unroll
                for (int nt = 0; nt < 8; nt++)
                    MMA16816(acc[mt][nt], af[mt], bf[nt][0], bf[nt][1]);
        }
        __syncthreads();
    }

    #pragma unroll
    for (int mt = 0; mt < 2; mt++) {
        int row = m0 + wm0 + mt * 16 + g;
        #pragma unroll
        for (int nt = 0; nt < 8; nt++) {
            int col = n0 + wn0 + nt * 8 + c2;
            *(__half2*)&C[(size_t)row       * N + col] = __floats2half2_rn(acc[mt][nt][0], acc[mt][nt][1]);
            *(__half2*)&C[(size_t)(row + 8) * N + col] = __floats2half2_rn(acc[mt][nt][2], acc[mt][nt][3]);
        }
    }
}

// ---------------- fused pairwise stage --------------------------------------
// EXACT 309.2us-winner config: 256 thr, 8 warps, warp tile 64x64,
// weight chunk 32 (8 per layer), smem 110KB.
static const int SMEM_FUSED = 128*264*2 + 2*256*40*2 + 2*256*4;

__device__ __forceinline__ void prefetch_w(const __half* __restrict__ Wt, int kc,
                                           __half (*sWbuf)[40], int tid)
{
    #pragma unroll
    for (int it = 0; it < 4; it++) {
        int idx = it * 256 + tid;
        int n = idx >> 2, c4 = idx & 3;
        asm volatile("cp.async.cg.shared.global [%0], [%1], 16;\n"
                     :: "r"(cvta_s(&sWbuf[n][c4 * 8])), "l"(Wt + n * 256 + kc * 32 + c4 * 8));
    }
    asm volatile("cp.async.commit_group;\n");
}

__global__ __launch_bounds__(256, 1) void k_fused(const float* __restrict__ bg1,
                                                  const float* __restrict__ bg2,
                                                  const float* __restrict__ bg3,
                                                  const float* __restrict__ bg4)
{
    extern __shared__ char smem[];
    __half (*sAct)[264]   = (__half(*)[264])smem;
    __half (*sW)[256][40] = (__half(*)[256][40])(smem + 128*264*2);
    float*  sCol          = (float*)(smem + 128*264*2 + 2*256*40*2);

    const int tid  = threadIdx.x;
    const int warp = tid >> 5, lane = tid & 31;
    const int g    = lane >> 2, c2 = (lane & 3) * 2;
    const int wm0  = (warp & 1) * 64;
    const int wn0  = (warp >> 1) * 64;
    const int ct   = blockIdx.x;
    const int b    = ct >> 3;
    const int i0   = (ct & 7) * 4;

    const __half* wts[3]    = {g_w2t, g_w3t, g_w4t};
    const float*  biases[3] = {bg2, bg3, bg4};

    prefetch_w(wts[0], 0, sW[0], tid);

    // ---- build: act[m][d] = relu(A[b,j,d] + B[b,i,d] + bg1[d]) ----
    {
        int m = tid >> 1, half = tid & 1;
        int i = i0 + (m >> 5), j = m & 31;
        const __half2* Ar = (const __half2*)g_AB + (size_t)(b * 32 + j) * 256 + half * 64;
        const __half2* Br = (const __half2*)g_AB + (size_t)(b * 32 + i) * 256 + 128 + half * 64;
        const float2*  bb = (const float2*)bg1 + half * 64;
        __half2* dst = (__half2*)&sAct[m][half * 128];
        #pragma unroll 8
        for (int cc = 0; cc < 64; cc++) {
            float2 a = __half22float2(Ar[cc]);
            float2 e = __half22float2(Br[cc]);
            float2 bi = bb[cc];
            dst[cc] = __floats2half2_rn(fmaxf(a.x + e.x + bi.x, 0.f),
                                        fmaxf(a.y + e.y + bi.y, 0.f));
        }
    }

    uint32_t aAddr[4], bOff[4];
    #pragma unroll
    for (int mt = 0; mt < 4; mt++)
        aAddr[mt] = cvta_s(&sAct[wm0 + mt * 16 + (lane & 15)][(lane >> 4) * 8]);
    #pragma unroll
    for (int p = 0; p < 4; p++)
        bOff[p] = ((wn0 + p * 16 + ((lane >> 4) & 1) * 8 + (lane & 7)) * 40
                   + ((lane >> 3) & 1) * 8) * 2;
    const uint32_t sWb = cvta_s(sW);
    const uint32_t wBufSz = 256 * 40 * 2;

    for (int L = 0; L < 3; L++) {
        const __half* Wt  = wts[L];
        const float* bias = biases[L];

        float acc[4][8][4];
        #pragma unroll
        for (int mt = 0; mt < 4; mt++)
            #pragma unroll
            for (int nt = 0; nt < 8; nt++)
                #pragma unroll
                for (int q = 0; q < 4; q++) acc[mt][nt][q] = 0.f;

        for (int kc = 0; kc < 8; kc++) {
            asm volatile("cp.async.wait_group 0;\n" ::: "memory");
            __syncthreads();
            if (kc < 7)     prefetch_w(Wt,       kc + 1, sW[(kc + 1) & 1], tid);
            else if (L < 2) prefetch_w(wts[L+1], 0,      sW[0],            tid);
            const uint32_t bbase = sWb + (kc & 1) * wBufSz;

            #pragma unroll
            for (int kk = 0; kk < 32; kk += 16) {
                const int kbase = kc * 32 + kk;
                uint32_t af[4][4], bf[8][2];
                #pragma unroll
                for (int mt = 0; mt < 4; mt++)
                    ldsm_x4(af[mt][0], af[mt][1], af[mt][2], af[mt][3],
                            aAddr[mt] + kbase * 2);
                #pragma unroll
                for (int p = 0; p < 4; p++)
                    ldsm_x4(bf[2*p][0], bf[2*p][1], bf[2*p+1][0], bf[2*p+1][1],
                            bbase + bOff[p] + kk * 2);
                #pragma unroll
                for (int mt = 0; mt < 4; mt++)
                    #pragma unroll
                    for (int nt = 0; nt < 8; nt++)
                        MMA16816(acc[mt][nt], af[mt], bf[nt][0], bf[nt][1]);
            }
        }
        __syncthreads();   // all warps done reading sAct for this layer

        if (L < 2) {
            #pragma unroll
            for (int mt = 0; mt < 4; mt++) {
                int row = wm0 + mt * 16 + g;
                #pragma unroll
                for (int nt = 0; nt < 8; nt++) {
                    int col = wn0 + nt * 8 + c2;
                    float b0 = bias[col], b1 = bias[col + 1];
                    *(__half2*)&sAct[row    ][col] =
                        __floats2half2_rn(fmaxf(acc[mt][nt][0] + b0, 0.f),
                                          fmaxf(acc[mt][nt][1] + b1, 0.f));
                    *(__half2*)&sAct[row + 8][col] =
                        __floats2half2_rn(fmaxf(acc[mt][nt][2] + b0, 0.f),
                                          fmaxf(acc[mt][nt][3] + b1, 0.f));
                }
            }
        } else {
            #pragma unroll
            for (int nt = 0; nt < 8; nt++) {
                int col = wn0 + nt * 8 + c2;
                float b0 = bias[col], b1 = bias[col + 1];
                float s0 = 0.f, s1 = 0.f;
                #pragma unroll
                for (int mt = 0; mt < 4; mt++) {
                    s0 += fmaxf(acc[mt][nt][0] + b0, 0.f) + fmaxf(acc[mt][nt][2] + b0, 0.f);
                    s1 += fmaxf(acc[mt][nt][1] + b1, 0.f) + fmaxf(acc[mt][nt][3] + b1, 0.f);
                }
                #pragma unroll
                for (int o = 4; o < 32; o <<= 1) {
                    s0 += __shfl_xor_sync(0xffffffffu, s0, o);
                    s1 += __shfl_xor_sync(0xffffffffu, s1, o);
                }
                if (lane < 4) {
                    sCol[(warp & 1) * 256 + wn0 + nt * 8 + lane * 2    ] = s0;
                    sCol[(warp & 1) * 256 + wn0 + nt * 8 + lane * 2 + 1] = s1;
                }
            }
            __syncthreads();
            g_part[(size_t)ct * 256 + tid] = sCol[tid] + sCol[256 + tid];
        }
    }
}

// ---------------- fp32 tail: 1024 threads, k-sliced layers ------------------
// One CTA per batch row. Layers 1-2: 4 k-slices per output col (64-deep loops);
// layer 3: 8 k-slices. Smem reductions between layers.
__global__ __launch_bounds__(1024) void k_tails(
    const float* __restrict__ Wf1,  const float* __restrict__ bf1,
    const float* __restrict__ Wfc2, const float* __restrict__ bfc2,
    const float* __restrict__ Wfc3, const float* __restrict__ bfc3,
    float* __restrict__ out)
{
    __shared__ float s0[256], s1[256], sp[4][256];
    const int b = blockIdx.x, tid = threadIdx.x;
    const int n = tid & 255, q = tid >> 8;      // q = 0..3

    // sum of the 8 per-CTA partials: q handles slices 2q, 2q+1
    sp[q][n] = g_part[(size_t)(b * 8 + 2 * q) * 256 + n]
             + g_part[(size_t)(b * 8 + 2 * q + 1) * 256 + n];
    __syncthreads();
    if (q == 0) s0[n] = (sp[0][n] + sp[1][n]) + (sp[2][n] + sp[3][n]);
    __syncthreads();

    // layer 1: s1 = relu(s0 @ Wf1 + bf1)
    {
        const int kb = q * 64;
        float p[4] = {0.f, 0.f, 0.f, 0.f};
        for (int k0 = 0; k0 < 64; k0 += 4) {
            #pragma unroll
            for (int u = 0; u < 4; u++)
                p[u] = fmaf(s0[kb + k0 + u], Wf1[(size_t)(kb + k0 + u) * 256 + n], p[u]);
        }
        sp[q][n] = (p[0] + p[1]) + (p[2] + p[3]);
        __syncthreads();
        if (q == 0)
            s1[n] = fmaxf(bf1[n] + (sp[0][n] + sp[1][n]) + (sp[2][n] + sp[3][n]), 0.f);
        __syncthreads();
    }

    // layer 2: s0 = relu(s1 @ Wfc2 + bfc2)
    {
        const int kb = q * 64;
        float p[4] = {0.f, 0.f, 0.f, 0.f};
        for (int k0 = 0; k0 < 64; k0 += 4) {
            #pragma unroll
            for (int u = 0; u < 4; u++)
                p[u] = fmaf(s1[kb + k0 + u], Wfc2[(size_t)(kb + k0 + u) * 256 + n], p[u]);
        }
        sp[q][n] = (p[0] + p[1]) + (p[2] + p[3]);
        __syncthreads();
        if (q == 0)
            s0[n] = fmaxf(bfc2[n] + (sp[0][n] + sp[1][n]) + (sp[2][n] + sp[3][n]), 0.f);
        __syncthreads();
    }

    // layer 3: out = s0 @ Wfc3 + bfc3  (128 cols, 8 k-slices of 32)
    {
        const int col = tid & 127, sl = tid >> 7;   // sl = 0..7
        const int kb = sl * 32;
        float p[4] = {0.f, 0.f, 0.f, 0.f};
        for (int k0 = 0; k0 < 32; k0 += 4) {
            #pragma unroll
            for (int u = 0; u < 4; u++)
                p[u] = fmaf(s0[kb + k0 + u], Wfc3[(size_t)(kb + k0 + u) * 128 + col], p[u]);
        }
        float* flat = &sp[0][0];                     // reuse as [8][128]
        flat[sl * 128 + col] = (p[0] + p[1]) + (p[2] + p[3]);
        __syncthreads();
        if (sl == 0) {
            float acc = bfc3[col];
            #pragma unroll
            for (int s = 0; s < 8; s++) acc += flat[s * 128 + col];
            out[(size_t)b * 128 + col] = acc;
        }
    }
}

// ---------------- host ------------------------------------------------------
extern "C" void kernel_launch(void* const* d_in, const int* in_sizes, int n_in,
                              void* d_out, int out_size)
{
    const float* x    = (const float*)d_in[0];
    const float* Wg1  = (const float*)d_in[1];
    const float* bg1  = (const float*)d_in[2];
    const float* Wg2  = (const float*)d_in[3];
    const float* bg2  = (const float*)d_in[4];
    const float* Wg3  = (const float*)d_in[5];
    const float* bg3  = (const float*)d_in[6];
    const float* Wg4  = (const float*)d_in[7];
    const float* bg4  = (const float*)d_in[8];
    const float* Wf1  = (const float*)d_in[9];
    const float* bf1  = (const float*)d_in[10];
    const float* Wfc2 = (const float*)d_in[11];
    const float* bfc2 = (const float*)d_in[12];
    const float* Wfc3 = (const float*)d_in[13];
    const float* bfc3 = (const float*)d_in[14];
    float* out = (float*)d_out;

    __half *xh, *w1t, *AB;
    cudaGetSymbolAddress((void**)&xh,  g_xh);
    cudaGetSymbolAddress((void**)&w1t, g_w1t);
    cudaGetSymbolAddress((void**)&AB,  g_AB);

    cudaFuncSetAttribute(k_fused, cudaFuncAttributeMaxDynamicSharedMemorySize, SMEM_FUSED);
    cudaFuncSetAttribute(k_gemm1, cudaFuncAttributeMaxDynamicSharedMemorySize, G1_SMEM);

    dim3 tb(32, 8);
    k_pre<<<9488, tb>>>(x, Wg1, Wg2, Wg3, Wg4, Wf1, Wfc2, Wfc3);                // 1
    k_gemm1<<<dim3(4, 32), 256, G1_SMEM>>>(xh, w1t, AB, 4096, 512, 2048);       // 2
    k_fused<<<1024, 256, SMEM_FUSED>>>(bg1, bg2, bg3, bg4);                     // 3
    k_tails<<<128, 1024>>>(Wf1, bf1, Wfc2, bfc2, Wfc3, bfc3, out);              // 4
}

// round 17
// speedup vs baseline: 1.0535x; 1.0017x over previous
#include <cuda_runtime.h>
#include <cuda_fp16.h>
#include <stdint.h>

// ---------------- scratch (__device__ globals; no allocations anywhere) ----
__device__ __half g_xh [4096u * 2048u];   // x transposed: row (b,p), K=2048 contiguous, fp16
__device__ __half g_w1t[512u  * 2048u];   // Wg1 as [n][k] fp16
__device__ __half g_w2t[256 * 256];       // Wg2^T fp16 [n][k]
__device__ __half g_w3t[256 * 256];
__device__ __half g_w4t[256 * 256];
__device__ __half g_AB [4096u * 512u];    // GEMM1 out: [(b,p)][512] (A | B)
__device__ float  g_part[1024 * 256];     // per-CTA partial column sums
__device__ float  g_sink;                 // L2-warm discard target (never read)

__device__ __forceinline__ uint32_t cvta_s(const void* p) {
    return (uint32_t)__cvta_generic_to_shared(p);
}
__device__ __forceinline__ void ldsm_x4(uint32_t& r0, uint32_t& r1, uint32_t& r2, uint32_t& r3,
                                        uint32_t addr) {
    asm volatile("ldmatrix.sync.aligned.m8n8.x4.shared.b16 {%0,%1,%2,%3}, [%4];\n"
                 : "=r"(r0), "=r"(r1), "=r"(r2), "=r"(r3) : "r"(addr));
}
#define MMA16816(acc, af, b0, b1)                                              \
    asm volatile(                                                              \
        "mma.sync.aligned.m16n8k16.row.col.f32.f16.f16.f32 "                   \
        "{%0,%1,%2,%3}, {%4,%5,%6,%7}, {%8,%9}, {%0,%1,%2,%3};\n"              \
        : "+f"(acc[0]), "+f"(acc[1]), "+f"(acc[2]), "+f"(acc[3])               \
        : "r"(af[0]), "r"(af[1]), "r"(af[2]), "r"(af[3]), "r"(b0), "r"(b1))

// ---------------- k_pre: all transposes + tail-weight L2 warm (one launch) --
__global__ void k_pre(const float* __restrict__ x, const float* __restrict__ Wg1,
                      const float* __restrict__ W2, const float* __restrict__ W3,
                      const float* __restrict__ W4,
                      const float* __restrict__ Wf1, const float* __restrict__ Wfc2,
                      const float* __restrict__ Wfc3)
{
    __shared__ float t[32][33];
    const int id = blockIdx.x;
    if (id >= 9408) {
        // L2 warm: stream tail weights; NaN-guard keeps loads alive (never true).
        int w = id - 9408;
        int tt = threadIdx.y * 32 + threadIdx.x;
        size_t g0 = (size_t)w * 2048 + (size_t)tt * 8;
        float s = 0.f;
        #pragma unroll
        for (int j = 0; j < 8; j++) {
            size_t g = g0 + j;
            float v;
            if (g < 65536)       v = Wf1 [g];
            else if (g < 131072) v = Wfc2[g - 65536];
            else                 v = Wfc3[g - 131072];
            s += v;
        }
        if (s != s) g_sink = s;
        return;
    }
    const float* inb; __half* outb; int R, C, r0, c0;
    if (id < 8192) {
        int z = id >> 6, yb = id & 63;
        inb = x + (size_t)z * 2048 * 32;
        outb = g_xh + (size_t)z * 2048 * 32;
        R = 2048; C = 32; r0 = yb * 32; c0 = 0;
    } else if (id < 9216) {
        int w = id - 8192;
        int half = w >> 9, rem = w & 511;
        int xb = rem & 7, yb = rem >> 3;
        inb = Wg1 + (size_t)half * 2048 * 256;
        outb = g_w1t + (size_t)half * 256 * 2048;
        R = 2048; C = 256; r0 = yb * 32; c0 = xb * 32;
    } else {
        int w = id - 9216;
        int which = w >> 6, rem = w & 63;
        int xb = rem & 7, yb = rem >> 3;
        const float* src[3] = {W2, W3, W4};
        __half* dst[3] = {g_w2t, g_w3t, g_w4t};
        inb = src[which]; outb = dst[which];
        R = 256; C = 256; r0 = yb * 32; c0 = xb * 32;
    }
    for (int i = threadIdx.y; i < 32; i += 8)
        t[i][threadIdx.x] = inb[(size_t)(r0 + i) * C + c0 + threadIdx.x];
    __syncthreads();
    for (int i = threadIdx.y; i < 32; i += 8)
        outb[(size_t)(c0 + i) * R + r0 + threadIdx.x] = __float2half(t[threadIdx.x][i]);
}

// ---------------- GEMM1: pipelined fp16 HMMA, BM=128 BN=128 BK=64 ----------
static const int G1_SMEM = 2 * (128 * 72 * 2) * 2;   // 73728 B

__device__ __forceinline__ void g1_issue(const __half* __restrict__ Ag,
                                         const __half* __restrict__ Bg,
                                         __half (*sA)[72], __half (*sB)[72],
                                         int K, int k0, int tid)
{
    #pragma unroll
    for (int it = 0; it < 4; it++) {
        int idx = it * 256 + tid;
        int row = idx >> 3, c8 = (idx & 7) * 8;
        asm volatile("cp.async.cg.shared.global [%0], [%1], 16;\n"
                     :: "r"(cvta_s(&sA[row][c8])), "l"(Ag + (size_t)row * K + k0 + c8));
        asm volatile("cp.async.cg.shared.global [%0], [%1], 16;\n"
                     :: "r"(cvta_s(&sB[row][c8])), "l"(Bg + (size_t)row * K + k0 + c8));
    }
    asm volatile("cp.async.commit_group;\n");
}

__global__ __launch_bounds__(256) void k_gemm1(const __half* __restrict__ A,
                                               const __half* __restrict__ Bt,
                                               __half* __restrict__ C,
                                               int M, int N, int K)
{
    extern __shared__ char dyn[];
    __half (*sA)[128][72] = (__half(*)[128][72])dyn;
    __half (*sB)[128][72] = (__half(*)[128][72])(dyn + 2 * 128 * 72 * 2);

    const int m0 = blockIdx.y * 128, n0 = blockIdx.x * 128;
    const int tid = threadIdx.x, warp = tid >> 5, lane = tid & 31;
    const int wm0 = (warp & 3) * 32;
    const int wn0 = (warp >> 2) * 64;
    const int g = lane >> 2, c2 = (lane & 3) * 2;

    const __half* Ag = A  + (size_t)m0 * K;
    const __half* Bg = Bt + (size_t)n0 * K;

    float acc[2][8][4];
    #pragma unroll
    for (int mt = 0; mt < 2; mt++)
        #pragma unroll
        for (int nt = 0; nt < 8; nt++)
            #pragma unroll
            for (int q = 0; q < 4; q++) acc[mt][nt][q] = 0.f;

    uint32_t aOff[2], bOff[4];
    #pragma unroll
    for (int mt = 0; mt < 2; mt++)
        aOff[mt] = ((wm0 + mt * 16 + (lane & 15)) * 72 + (lane >> 4) * 8) * 2;
    #pragma unroll
    for (int p = 0; p < 4; p++)
        bOff[p] = ((wn0 + p * 16 + ((lane >> 4) & 1) * 8 + (lane & 7)) * 72
                   + ((lane >> 3) & 1) * 8) * 2;
    const uint32_t sAb = cvta_s(sA), sBb = cvta_s(sB);
    const uint32_t stgA = 128 * 72 * 2;

    const int NC = K / 64;
    g1_issue(Ag, Bg, sA[0], sB[0], K, 0, tid);

    for (int kc = 0; kc < NC; kc++) {
        if (kc + 1 < NC) {
            g1_issue(Ag, Bg, sA[(kc + 1) & 1], sB[(kc + 1) & 1], K, (kc + 1) * 64, tid);
            asm volatile("cp.async.wait_group 1;\n" ::: "memory");
        } else {
            asm volatile("cp.async.wait_group 0;\n" ::: "memory");
        }
        __syncthreads();
        const uint32_t abase = sAb + (kc & 1) * stgA;
        const uint32_t bbase = sBb + (kc & 1) * stgA;
        #pragma unroll
        for (int kk = 0; kk < 64; kk += 16) {
            uint32_t af[2][4], bf[8][2];
            #pragma unroll
            for (int mt = 0; mt < 2; mt++)
                ldsm_x4(af[mt][0], af[mt][1], af[mt][2], af[mt][3],
                        abase + aOff[mt] + kk * 2);
            #pragma unroll
            for (int p = 0; p < 4; p++)
                ldsm_x4(bf[2*p][0], bf[2*p][1], bf[2*p+1][0], bf[2*p+1][1],
                        bbase + bOff[p] + kk * 2);
            #pragma unroll
            for (int mt = 0; mt < 2; mt++)
                #pragma unroll
                for (int nt = 0; nt < 8; nt++)
                    MMA16816(acc[mt][nt], af[mt], bf[nt][0], bf[nt][1]);
        }
        __syncthreads();
    }

    #pragma unroll
    for (int mt = 0; mt < 2; mt++) {
        int row = m0 + wm0 + mt * 16 + g;
        #pragma unroll
        for (int nt = 0; nt < 8; nt++) {
            int col = n0 + wn0 + nt * 8 + c2;
            *(__half2*)&C[(size_t)row       * N + col] = __floats2half2_rn(acc[mt][nt][0], acc[mt][nt][1]);
            *(__half2*)&C[(size_t)(row + 8) * N + col] = __floats2half2_rn(acc[mt][nt][2], acc[mt][nt][3]);
        }
    }
}

// ---------------- fused pairwise stage --------------------------------------
// EXACT best config: 256 thr, 8 warps, warp tile 64x64, weight chunk 32.
static const int SMEM_FUSED = 128*264*2 + 2*256*40*2 + 2*256*4;

__device__ __forceinline__ void prefetch_w(const __half* __restrict__ Wt, int kc,
                                           __half (*sWbuf)[40], int tid)
{
    #pragma unroll
    for (int it = 0; it < 4; it++) {
        int idx = it * 256 + tid;
        int n = idx >> 2, c4 = idx & 3;
        asm volatile("cp.async.cg.shared.global [%0], [%1], 16;\n"
                     :: "r"(cvta_s(&sWbuf[n][c4 * 8])), "l"(Wt + n * 256 + kc * 32 + c4 * 8));
    }
    asm volatile("cp.async.commit_group;\n");
}

__global__ __launch_bounds__(256, 1) void k_fused(const float* __restrict__ bg1,
                                                  const float* __restrict__ bg2,
                                                  const float* __restrict__ bg3,
                                                  const float* __restrict__ bg4)
{
    extern __shared__ char smem[];
    __half (*sAct)[264]   = (__half(*)[264])smem;
    __half (*sW)[256][40] = (__half(*)[256][40])(smem + 128*264*2);
    float*  sCol          = (float*)(smem + 128*264*2 + 2*256*40*2);

    const int tid  = threadIdx.x;
    const int warp = tid >> 5, lane = tid & 31;
    const int g    = lane >> 2, c2 = (lane & 3) * 2;
    const int wm0  = (warp & 1) * 64;
    const int wn0  = (warp >> 1) * 64;
    const int ct   = blockIdx.x;
    const int b    = ct >> 3;
    const int i0   = (ct & 7) * 4;

    const __half* wts[3]    = {g_w2t, g_w3t, g_w4t};
    const float*  biases[3] = {bg2, bg3, bg4};

    prefetch_w(wts[0], 0, sW[0], tid);

    // ---- build: act[m][d] = relu(A[b,j,d] + B[b,i,d] + bg1[d]) ----
    {
        int m = tid >> 1, half = tid & 1;
        int i = i0 + (m >> 5), j = m & 31;
        const __half2* Ar = (const __half2*)g_AB + (size_t)(b * 32 + j) * 256 + half * 64;
        const __half2* Br = (const __half2*)g_AB + (size_t)(b * 32 + i) * 256 + 128 + half * 64;
        const float2*  bb = (const float2*)bg1 + half * 64;
        __half2* dst = (__half2*)&sAct[m][half * 128];
        #pragma unroll 8
        for (int cc = 0; cc < 64; cc++) {
            float2 a = __half22float2(Ar[cc]);
            float2 e = __half22float2(Br[cc]);
            float2 bi = bb[cc];
            dst[cc] = __floats2half2_rn(fmaxf(a.x + e.x + bi.x, 0.f),
                                        fmaxf(a.y + e.y + bi.y, 0.f));
        }
    }

    uint32_t aAddr[4], bOff[4];
    #pragma unroll
    for (int mt = 0; mt < 4; mt++)
        aAddr[mt] = cvta_s(&sAct[wm0 + mt * 16 + (lane & 15)][(lane >> 4) * 8]);
    #pragma unroll
    for (int p = 0; p < 4; p++)
        bOff[p] = ((wn0 + p * 16 + ((lane >> 4) & 1) * 8 + (lane & 7)) * 40
                   + ((lane >> 3) & 1) * 8) * 2;
    const uint32_t sWb = cvta_s(sW);
    const uint32_t wBufSz = 256 * 40 * 2;

    for (int L = 0; L < 3; L++) {
        const __half* Wt  = wts[L];
        const float* bias = biases[L];

        float acc[4][8][4];
        #pragma unroll
        for (int mt = 0; mt < 4; mt++)
            #pragma unroll
            for (int nt = 0; nt < 8; nt++)
                #pragma unroll
                for (int q = 0; q < 4; q++) acc[mt][nt][q] = 0.f;

        for (int kc = 0; kc < 8; kc++) {
            asm volatile("cp.async.wait_group 0;\n" ::: "memory");
            __syncthreads();
            if (kc < 7)     prefetch_w(Wt,       kc + 1, sW[(kc + 1) & 1], tid);
            else if (L < 2) prefetch_w(wts[L+1], 0,      sW[0],            tid);
            const uint32_t bbase = sWb + (kc & 1) * wBufSz;

            #pragma unroll
            for (int kk = 0; kk < 32; kk += 16) {
                const int kbase = kc * 32 + kk;
                uint32_t af[4][4], bf[8][2];
                #pragma unroll
                for (int mt = 0; mt < 4; mt++)
                    ldsm_x4(af[mt][0], af[mt][1], af[mt][2], af[mt][3],
                            aAddr[mt] + kbase * 2);
                #pragma unroll
                for (int p = 0; p < 4; p++)
                    ldsm_x4(bf[2*p][0], bf[2*p][1], bf[2*p+1][0], bf[2*p+1][1],
                            bbase + bOff[p] + kk * 2);
                #pragma unroll
                for (int mt = 0; mt < 4; mt++)
                    #pragma unroll
                    for (int nt = 0; nt < 8; nt++)
                        MMA16816(acc[mt][nt], af[mt], bf[nt][0], bf[nt][1]);
            }
        }
        __syncthreads();   // all warps done reading sAct for this layer

        if (L < 2) {
            #pragma unroll
            for (int mt = 0; mt < 4; mt++) {
                int row = wm0 + mt * 16 + g;
                #pragma unroll
                for (int nt = 0; nt < 8; nt++) {
                    int col = wn0 + nt * 8 + c2;
                    float b0 = bias[col], b1 = bias[col + 1];
                    *(__half2*)&sAct[row    ][col] =
                        __floats2half2_rn(fmaxf(acc[mt][nt][0] + b0, 0.f),
                                          fmaxf(acc[mt][nt][1] + b1, 0.f));
                    *(__half2*)&sAct[row + 8][col] =
                        __floats2half2_rn(fmaxf(acc[mt][nt][2] + b0, 0.f),
                                          fmaxf(acc[mt][nt][3] + b1, 0.f));
                }
            }
        } else {
            #pragma unroll
            for (int nt = 0; nt < 8; nt++) {
                int col = wn0 + nt * 8 + c2;
                float b0 = bias[col], b1 = bias[col + 1];
                float s0 = 0.f, s1 = 0.f;
                #pragma unroll
                for (int mt = 0; mt < 4; mt++) {
                    s0 += fmaxf(acc[mt][nt][0] + b0, 0.f) + fmaxf(acc[mt][nt][2] + b0, 0.f);
                    s1 += fmaxf(acc[mt][nt][1] + b1, 0.f) + fmaxf(acc[mt][nt][3] + b1, 0.f);
                }
                #pragma unroll
                for (int o = 4; o < 32; o <<= 1) {
                    s0 += __shfl_xor_sync(0xffffffffu, s0, o);
                    s1 += __shfl_xor_sync(0xffffffffu, s1, o);
                }
                if (lane < 4) {
                    sCol[(warp & 1) * 256 + wn0 + nt * 8 + lane * 2    ] = s0;
                    sCol[(warp & 1) * 256 + wn0 + nt * 8 + lane * 2 + 1] = s1;
                }
            }
            __syncthreads();
            g_part[(size_t)ct * 256 + tid] = sCol[tid] + sCol[256 + tid];
        }
    }
}

// ---------------- fp32 tail: 1024 threads, k-sliced layers, MLP=8 -----------
__global__ __launch_bounds__(1024) void k_tails(
    const float* __restrict__ Wf1,  const float* __restrict__ bf1,
    const float* __restrict__ Wfc2, const float* __restrict__ bfc2,
    const float* __restrict__ Wfc3, const float* __restrict__ bfc3,
    float* __restrict__ out)
{
    __shared__ float s0[256], s1[256], sp[4][256];
    const int b = blockIdx.x, tid = threadIdx.x;
    const int n = tid & 255, q = tid >> 8;      // q = 0..3

    // sum of the 8 per-CTA partials: q handles slices 2q, 2q+1
    sp[q][n] = g_part[(size_t)(b * 8 + 2 * q) * 256 + n]
             + g_part[(size_t)(b * 8 + 2 * q + 1) * 256 + n];
    __syncthreads();
    if (q == 0) s0[n] = (sp[0][n] + sp[1][n]) + (sp[2][n] + sp[3][n]);
    __syncthreads();

    // layer 1: s1 = relu(s0 @ Wf1 + bf1)   (k-slice of 64, 8 accumulators)
    {
        const int kb = q * 64;
        float p[8] = {0.f, 0.f, 0.f, 0.f, 0.f, 0.f, 0.f, 0.f};
        #pragma unroll
        for (int k0 = 0; k0 < 64; k0 += 8) {
            #pragma unroll
            for (int u = 0; u < 8; u++)
                p[u] = fmaf(s0[kb + k0 + u], Wf1[(size_t)(kb + k0 + u) * 256 + n], p[u]);
        }
        sp[q][n] = ((p[0] + p[1]) + (p[2] + p[3])) + ((p[4] + p[5]) + (p[6] + p[7]));
        __syncthreads();
        if (q == 0)
            s1[n] = fmaxf(bf1[n] + (sp[0][n] + sp[1][n]) + (sp[2][n] + sp[3][n]), 0.f);
        __syncthreads();
    }

    // layer 2: s0 = relu(s1 @ Wfc2 + bfc2)
    {
        const int kb = q * 64;
        float p[8] = {0.f, 0.f, 0.f, 0.f, 0.f, 0.f, 0.f, 0.f};
        #pragma unroll
        for (int k0 = 0; k0 < 64; k0 += 8) {
            #pragma unroll
            for (int u = 0; u < 8; u++)
                p[u] = fmaf(s1[kb + k0 + u], Wfc2[(size_t)(kb + k0 + u) * 256 + n], p[u]);
        }
        sp[q][n] = ((p[0] + p[1]) + (p[2] + p[3])) + ((p[4] + p[5]) + (p[6] + p[7]));
        __syncthreads();
        if (q == 0)
            s0[n] = fmaxf(bfc2[n] + (sp[0][n] + sp[1][n]) + (sp[2][n] + sp[3][n]), 0.f);
        __syncthreads();
    }

    // layer 3: out = s0 @ Wfc3 + bfc3  (128 cols, 8 k-slices of 32, MLP=8)
    {
        const int col = tid & 127, sl = tid >> 7;   // sl = 0..7
        const int kb = sl * 32;
        float p[8] = {0.f, 0.f, 0.f, 0.f, 0.f, 0.f, 0.f, 0.f};
        #pragma unroll
        for (int k0 = 0; k0 < 32; k0 += 8) {
            #pragma unroll
            for (int u = 0; u < 8; u++)
                p[u] = fmaf(s0[kb + k0 + u], Wfc3[(size_t)(kb + k0 + u) * 128 + col], p[u]);
        }
        float* flat = &sp[0][0];                     // reuse as [8][128]
        flat[sl * 128 + col] = ((p[0] + p[1]) + (p[2] + p[3]))
                             + ((p[4] + p[5]) + (p[6] + p[7]));
        __syncthreads();
        if (sl == 0) {
            float acc = bfc3[col];
            #pragma unroll
            for (int s = 0; s < 8; s++) acc += flat[s * 128 + col];
            out[(size_t)b * 128 + col] = acc;
        }
    }
}

// ---------------- host ------------------------------------------------------
extern "C" void kernel_launch(void* const* d_in, const int* in_sizes, int n_in,
                              void* d_out, int out_size)
{
    const float* x    = (const float*)d_in[0];
    const float* Wg1  = (const float*)d_in[1];
    const float* bg1  = (const float*)d_in[2];
    const float* Wg2  = (const float*)d_in[3];
    const float* bg2  = (const float*)d_in[4];
    const float* Wg3  = (const float*)d_in[5];
    const float* bg3  = (const float*)d_in[6];
    const float* Wg4  = (const float*)d_in[7];
    const float* bg4  = (const float*)d_in[8];
    const float* Wf1  = (const float*)d_in[9];
    const float* bf1  = (const float*)d_in[10];
    const float* Wfc2 = (const float*)d_in[11];
    const float* bfc2 = (const float*)d_in[12];
    const float* Wfc3 = (const float*)d_in[13];
    const float* bfc3 = (const float*)d_in[14];
    float* out = (float*)d_out;

    __half *xh, *w1t, *AB;
    cudaGetSymbolAddress((void**)&xh,  g_xh);
    cudaGetSymbolAddress((void**)&w1t, g_w1t);
    cudaGetSymbolAddress((void**)&AB,  g_AB);

    cudaFuncSetAttribute(k_fused, cudaFuncAttributeMaxDynamicSharedMemorySize, SMEM_FUSED);
    cudaFuncSetAttribute(k_gemm1, cudaFuncAttributeMaxDynamicSharedMemorySize, G1_SMEM);

    dim3 tb(32, 8);
    k_pre<<<9488, tb>>>(x, Wg1, Wg2, Wg3, Wg4, Wf1, Wfc2, Wfc3);                // 1
    k_gemm1<<<dim3(4, 32), 256, G1_SMEM>>>(xh, w1t, AB, 4096, 512, 2048);       // 2
    k_fused<<<1024, 256, SMEM_FUSED>>>(bg1, bg2, bg3, bg4);                     // 3
    k_tails<<<128, 1024>>>(Wf1, bf1, Wfc2, bfc2, Wfc3, bfc3, out);              // 4
}